// round 15
// baseline (speedup 1.0000x reference)
#include <cuda_runtime.h>
#include <cuda_fp16.h>
#include <cstdint>

#define NN 50000
#define EE 800000
#define DD 96
#define FF 128

// ---------------- scratch ----------------
__device__ __align__(16) __half g_hA[NN * DD];
__device__ __align__(16) __half g_hB[NN * DD];
__device__ __align__(16) __half g_xh[NN * FF];      // fp16 copy of x
__device__ __align__(16) float  g_T[NN * 3 * DD];   // [N][288]: root | rel0 | rel1 (fp32)
__device__ __align__(16) __half g_WfT[FF * DD];     // fp16 transposed Wf
__device__ __align__(16) __half g_Wc[3 * DD * DD];  // fp16 [root | W0 | W1]
__device__ int g_deg[2 * NN];
__device__ int g_cur[2 * NN];
__device__ int g_rowptr[2 * NN + 1];
__device__ int g_col[EE];
__device__ int g_bpart[256];

// ---------------- prep: zero deg + convert/transpose weights ----------------
__global__ void k_prep(const float* __restrict__ Wf, const float* __restrict__ root,
                       const float* __restrict__ W,
                       __half* __restrict__ WfT, __half* __restrict__ Wc,
                       int* __restrict__ deg, int N2) {
    int i = blockIdx.x * blockDim.x + threadIdx.x;
    if (i < N2) deg[i] = 0;
    if (i < DD * FF) {
        int d = i >> 7, k = i & 127;
        WfT[k * DD + d] = __float2half_rn(Wf[i]);
    }
    if (i < 3 * DD * DD)
        Wc[i] = __float2half_rn((i < DD * DD) ? root[i] : W[i - DD * DD]);
}

// ---------------- x -> fp16 copy ----------------
__global__ void k_xh(const float* __restrict__ x, __half* __restrict__ xh, int total4) {
    int i = blockIdx.x * blockDim.x + threadIdx.x;
    if (i >= total4) return;
    float4 v = __ldg((const float4*)x + i);
    __half2* o = (__half2*)xh + 2 * i;
    o[0] = __floats2half2_rn(v.x, v.y);
    o[1] = __floats2half2_rn(v.z, v.w);
}

// ---------------- CSR build ----------------
__global__ void k_hist(const int* __restrict__ ei, const float* __restrict__ attr,
                       int* __restrict__ deg, int E) {
    int e = (blockIdx.x * blockDim.x + threadIdx.x) * 2;
    if (e >= E) return;
    int2 d2 = *(const int2*)(ei + E + e);
    float4 a4 = *(const float4*)(attr + 2 * e);
    atomicAdd(&deg[2 * d2.x + (a4.y > a4.x ? 1 : 0)], 1);
    if (e + 1 < E)
        atomicAdd(&deg[2 * d2.y + (a4.w > a4.z ? 1 : 0)], 1);
}

__global__ __launch_bounds__(1024) void k_scanA(const int* __restrict__ deg,
                                                int* __restrict__ bpart, int N2) {
    __shared__ int red[32];
    int t = threadIdx.x;
    int i = blockIdx.x * 1024 + t;
    int v = (i < N2) ? deg[i] : 0;
#pragma unroll
    for (int o = 16; o; o >>= 1) v += __shfl_down_sync(~0u, v, o);
    if ((t & 31) == 0) red[t >> 5] = v;
    __syncthreads();
    if (t < 32) {
        int s = red[t];
#pragma unroll
        for (int o = 16; o; o >>= 1) s += __shfl_down_sync(~0u, s, o);
        if (t == 0) bpart[blockIdx.x] = s;
    }
}

__global__ __launch_bounds__(1024) void k_scanC(const int* __restrict__ deg,
                                                const int* __restrict__ bpart,
                                                int* __restrict__ rowptr,
                                                int* __restrict__ cur, int N2, int nb) {
    __shared__ int sm[1024];
    __shared__ int bp[128];
    int t = threadIdx.x;
    if (t < 128) bp[t] = (t < nb) ? __ldg(&bpart[t]) : 0;
    __syncthreads();
#pragma unroll
    for (int o = 1; o < 128; o <<= 1) {
        int u = 0;
        if (t < 128 && t >= o) u = bp[t - o];
        __syncthreads();
        if (t < 128) bp[t] += u;
        __syncthreads();
    }
    int off = (blockIdx.x == 0) ? 0 : bp[blockIdx.x - 1];

    int i = blockIdx.x * 1024 + t;
    int v = (i < N2) ? deg[i] : 0;
    sm[t] = v;
    __syncthreads();
#pragma unroll
    for (int o = 1; o < 1024; o <<= 1) {
        int u = (t >= o) ? sm[t - o] : 0;
        __syncthreads();
        sm[t] += u;
        __syncthreads();
    }
    int pos = off + sm[t] - v;
    if (i < N2) {
        rowptr[i] = pos;
        cur[i] = pos;
        if (i == N2 - 1) rowptr[N2] = pos + v;
    }
}

__global__ void k_fill(const int* __restrict__ ei, const float* __restrict__ attr,
                       int* __restrict__ cur, int* __restrict__ col, int E) {
    int e = (blockIdx.x * blockDim.x + threadIdx.x) * 2;
    if (e >= E) return;
    int2 s2 = *(const int2*)(ei + e);
    int2 d2 = *(const int2*)(ei + E + e);
    float4 a4 = *(const float4*)(attr + 2 * e);
    {
        int seg = 2 * d2.x + (a4.y > a4.x ? 1 : 0);
        col[atomicAdd(&cur[seg], 1)] = s2.x;
    }
    if (e + 1 < E) {
        int seg = 2 * d2.y + (a4.w > a4.z ? 1 : 0);
        col[atomicAdd(&cur[seg], 1)] = s2.y;
    }
}

// ---------------- fp16 MMA GEMM: full-K single-stage smem + ldmatrix ----------------
__device__ __forceinline__ void mma_f16(float* c, const uint32_t* a, uint32_t b0, uint32_t b1) {
    asm volatile("mma.sync.aligned.m16n8k16.row.col.f32.f16.f16.f32 "
        "{%0,%1,%2,%3}, {%4,%5,%6,%7}, {%8,%9}, {%0,%1,%2,%3};"
        : "+f"(c[0]), "+f"(c[1]), "+f"(c[2]), "+f"(c[3])
        : "r"(a[0]), "r"(a[1]), "r"(a[2]), "r"(a[3]), "r"(b0), "r"(b1));
}
__device__ __forceinline__ void ldsm4(uint32_t* r, uint32_t addr) {
    asm volatile("ldmatrix.sync.aligned.m8n8.x4.shared.b16 {%0,%1,%2,%3}, [%4];"
        : "=r"(r[0]), "=r"(r[1]), "=r"(r[2]), "=r"(r[3]) : "r"(addr));
}
__device__ __forceinline__ void ldsm4t(uint32_t* r, uint32_t addr) {
    asm volatile("ldmatrix.sync.aligned.m8n8.x4.trans.shared.b16 {%0,%1,%2,%3}, [%4];"
        : "=r"(r[0]), "=r"(r[1]), "=r"(r[2]), "=r"(r[3]) : "r"(addr));
}
__device__ __forceinline__ void cp16(uint32_t saddr, const void* gaddr, int srcsize) {
    asm volatile("cp.async.cg.shared.global [%0], [%1], 16, %2;"
                 :: "r"(saddr), "l"(gaddr), "r"(srcsize));
}

#define BS_LDH 104    // halves per B smem row

// flags: bit0 = relu, bit2 = fp16 output (Ch), else fp32 (Cf)
template <int K>
__global__ __launch_bounds__(256, 3) void k_gemm(
    const __half* __restrict__ A, int M,
    const __half* __restrict__ B0, const __half* __restrict__ B1, const __half* __restrict__ B2,
    float* __restrict__ Cf, __half* __restrict__ Ch, int ldc,
    const float* __restrict__ bias, int flags)
{
    constexpr int AS_LDH = K + 8;            // padded A row stride (halves)
    constexpr int ASZH = 128 * AS_LDH;
    constexpr int APIECES = 128 * (K / 8);   // 16B pieces for A
    constexpr int BPIECES = K * 12;          // 16B pieces for B

    extern __shared__ char smem[];
    const __half* B = (blockIdx.y == 0) ? B0 : ((blockIdx.y == 1) ? B1 : B2);

    int tid = threadIdx.x;
    int lane = tid & 31;
    int warp = tid >> 5;
    int g = lane >> 2, tig = lane & 3;
    int mw = warp & 3;
    int nw = warp >> 2;
    int rowblock = blockIdx.x * 128;

    uint32_t sbase = (uint32_t)__cvta_generic_to_shared(smem);

    // stage everything once
    for (int p = tid; p < APIECES; p += 256) {
        int row = p / (K / 8), kq = (p % (K / 8)) * 8;
        int gr = rowblock + row;
        cp16(sbase + (uint32_t)(row * AS_LDH + kq) * 2u,
             A + (size_t)gr * K + kq, (gr < M) ? 16 : 0);
    }
    for (int p = tid; p < BPIECES; p += 256) {
        int kr = p / 12, nq = (p % 12) * 8;
        cp16(sbase + (uint32_t)(ASZH + kr * BS_LDH + nq) * 2u,
             B + (size_t)kr * 96 + nq, 16);
    }
    asm volatile("cp.async.commit_group;" ::: "memory");

    float c[2][6][4];
#pragma unroll
    for (int i = 0; i < 2; i++)
#pragma unroll
        for (int j = 0; j < 6; j++)
#pragma unroll
            for (int q = 0; q < 4; q++) c[i][j][q] = 0.f;

    asm volatile("cp.async.wait_group 0;" ::: "memory");
    __syncthreads();

    uint32_t abase = sbase;
    uint32_t bbase = sbase + (uint32_t)ASZH * 2u;
#pragma unroll
    for (int k16 = 0; k16 < K; k16 += 16) {
        uint32_t a[2][4];
#pragma unroll
        for (int mt = 0; mt < 2; mt++) {
            int rb = mw * 32 + mt * 16;
            uint32_t addr = abase +
                (uint32_t)((rb + (lane & 15)) * AS_LDH + k16 + ((lane >> 4) << 3)) * 2u;
            ldsm4(a[mt], addr);
        }
        uint32_t b[3][4];
#pragma unroll
        for (int ntp = 0; ntp < 3; ntp++) {
            int cb = nw * 48 + ntp * 16;
            uint32_t addr = bbase +
                (uint32_t)((k16 + (lane & 15)) * BS_LDH + cb + ((lane & 16) ? 8 : 0)) * 2u;
            ldsm4t(b[ntp], addr);
        }
#pragma unroll
        for (int nt = 0; nt < 6; nt++) {
            uint32_t b0 = b[nt >> 1][(nt & 1) * 2];
            uint32_t b1 = b[nt >> 1][(nt & 1) * 2 + 1];
            mma_f16(c[0][nt], a[0], b0, b1);
            mma_f16(c[1][nt], a[1], b0, b1);
        }
    }

    int colchunk = blockIdx.y * 96;
    int relu = flags & 1, h16 = flags & 4;
#pragma unroll
    for (int mt = 0; mt < 2; mt++) {
        int r0 = rowblock + mw * 32 + mt * 16 + g;
        int r1 = r0 + 8;
#pragma unroll
        for (int nt = 0; nt < 6; nt++) {
            int col = nw * 48 + nt * 8 + 2 * tig;
            float bx = 0.f, by = 0.f;
            if (bias) { bx = __ldg(bias + col); by = __ldg(bias + col + 1); }
            float v0 = c[mt][nt][0] + bx, v1 = c[mt][nt][1] + by;
            float v2 = c[mt][nt][2] + bx, v3 = c[mt][nt][3] + by;
            if (relu) {
                v0 = fmaxf(v0, 0.f); v1 = fmaxf(v1, 0.f);
                v2 = fmaxf(v2, 0.f); v3 = fmaxf(v3, 0.f);
            }
            if (h16) {
                if (r0 < M) *(__half2*)(Ch + (size_t)r0 * ldc + col) = __floats2half2_rn(v0, v1);
                if (r1 < M) *(__half2*)(Ch + (size_t)r1 * ldc + col) = __floats2half2_rn(v2, v3);
            } else {
                if (r0 < M) *(float2*)(Cf + (size_t)r0 * ldc + colchunk + col) = make_float2(v0, v1);
                if (r1 < M) *(float2*)(Cf + (size_t)r1 * ldc + colchunk + col) = make_float2(v2, v3);
            }
        }
    }
}

#define SMEM_LIN ((128 * (FF + 8) + FF * BS_LDH) * 2)
#define SMEM_CNV ((128 * (DD + 8) + DD * BS_LDH) * 2)

// ---------------- fused float4 gather + mean + root + bias + relu ----------------
__global__ void k_aggout(const float* __restrict__ T, const int* __restrict__ rowptr,
                         const int* __restrict__ col, const float* __restrict__ bias,
                         float* __restrict__ outf, __half* __restrict__ outh,
                         int N, int tohalf) {
    int warpi = (blockIdx.x * blockDim.x + threadIdx.x) >> 5;
    int lane = threadIdx.x & 31;
    if (warpi >= N) return;
    int n = warpi;
    int e00 = __ldg(&rowptr[2 * n]);
    int e01 = __ldg(&rowptr[2 * n + 1]);
    int e11 = __ldg(&rowptr[2 * n + 2]);
    int cl = (lane < 24) ? lane : 23;

    float4 x = make_float4(0.f, 0.f, 0.f, 0.f);
    float4 y = make_float4(0.f, 0.f, 0.f, 0.f);

    int e = e00;
    for (; e + 3 < e01; e += 4) {
        const float4* p0 = (const float4*)(T + (size_t)__ldg(&col[e])     * 288 + 96);
        const float4* p1 = (const float4*)(T + (size_t)__ldg(&col[e + 1]) * 288 + 96);
        const float4* p2 = (const float4*)(T + (size_t)__ldg(&col[e + 2]) * 288 + 96);
        const float4* p3 = (const float4*)(T + (size_t)__ldg(&col[e + 3]) * 288 + 96);
        float4 v0 = __ldg(p0 + cl), v1 = __ldg(p1 + cl), v2 = __ldg(p2 + cl), v3 = __ldg(p3 + cl);
        x.x += (v0.x + v1.x) + (v2.x + v3.x);
        x.y += (v0.y + v1.y) + (v2.y + v3.y);
        x.z += (v0.z + v1.z) + (v2.z + v3.z);
        x.w += (v0.w + v1.w) + (v2.w + v3.w);
    }
    for (; e < e01; e++) {
        const float4* p = (const float4*)(T + (size_t)__ldg(&col[e]) * 288 + 96);
        float4 v = __ldg(p + cl);
        x.x += v.x; x.y += v.y; x.z += v.z; x.w += v.w;
    }
    e = e01;
    for (; e + 3 < e11; e += 4) {
        const float4* p0 = (const float4*)(T + (size_t)__ldg(&col[e])     * 288 + 192);
        const float4* p1 = (const float4*)(T + (size_t)__ldg(&col[e + 1]) * 288 + 192);
        const float4* p2 = (const float4*)(T + (size_t)__ldg(&col[e + 2]) * 288 + 192);
        const float4* p3 = (const float4*)(T + (size_t)__ldg(&col[e + 3]) * 288 + 192);
        float4 v0 = __ldg(p0 + cl), v1 = __ldg(p1 + cl), v2 = __ldg(p2 + cl), v3 = __ldg(p3 + cl);
        y.x += (v0.x + v1.x) + (v2.x + v3.x);
        y.y += (v0.y + v1.y) + (v2.y + v3.y);
        y.z += (v0.z + v1.z) + (v2.z + v3.z);
        y.w += (v0.w + v1.w) + (v2.w + v3.w);
    }
    for (; e < e11; e++) {
        const float4* p = (const float4*)(T + (size_t)__ldg(&col[e]) * 288 + 192);
        float4 v = __ldg(p + cl);
        y.x += v.x; y.y += v.y; y.z += v.z; y.w += v.w;
    }

    if (lane < 24) {
        float i0 = 1.f / fmaxf((float)(e01 - e00), 1.f);
        float i1 = 1.f / fmaxf((float)(e11 - e01), 1.f);
        float4 r = __ldg((const float4*)(T + (size_t)n * 288) + lane);
        float4 b = __ldg((const float4*)bias + lane);
        float4 o;
        o.x = fmaxf(b.x + r.x + x.x * i0 + y.x * i1, 0.f);
        o.y = fmaxf(b.y + r.y + x.y * i0 + y.y * i1, 0.f);
        o.z = fmaxf(b.z + r.z + x.z * i0 + y.z * i1, 0.f);
        o.w = fmaxf(b.w + r.w + x.w * i0 + y.w * i1, 0.f);
        if (tohalf) {
            __half* p = outh + (size_t)n * DD + 4 * lane;
            *(__half2*)p       = __floats2half2_rn(o.x, o.y);
            *(__half2*)(p + 2) = __floats2half2_rn(o.z, o.w);
        } else {
            *((float4*)(outf + (size_t)n * DD) + lane) = o;
        }
    }
}

// ---------------- launch ----------------
extern "C" void kernel_launch(void* const* d_in, const int* in_sizes, int n_in,
                              void* d_out, int out_size) {
    const float* x    = (const float*)d_in[0];
    const int*   ei   = (const int*)d_in[1];
    const float* attr = (const float*)d_in[2];
    const float* Wf   = (const float*)d_in[3];
    const float* bf   = (const float*)d_in[4];
    const float* W    = (const float*)d_in[5];
    const float* root = (const float*)d_in[6];
    const float* bias = (const float*)d_in[7];
    float* out = (float*)d_out;

    int E = in_sizes[1] / 2;
    int N = in_sizes[0] / FF;
    int N2 = 2 * N;
    int nb = (N2 + 1023) / 1024;

    void *pA, *pB, *pX, *pT, *pWfT, *pWc, *pdg, *prp, *pc, *pcol, *pbp;
    cudaGetSymbolAddress(&pA, g_hA);
    cudaGetSymbolAddress(&pB, g_hB);
    cudaGetSymbolAddress(&pX, g_xh);
    cudaGetSymbolAddress(&pT, g_T);
    cudaGetSymbolAddress(&pWfT, g_WfT);
    cudaGetSymbolAddress(&pWc, g_Wc);
    cudaGetSymbolAddress(&pdg, g_deg);
    cudaGetSymbolAddress(&prp, g_rowptr);
    cudaGetSymbolAddress(&pc, g_cur);
    cudaGetSymbolAddress(&pcol, g_col);
    cudaGetSymbolAddress(&pbp, g_bpart);

    cudaFuncSetAttribute(k_gemm<FF>, cudaFuncAttributeMaxDynamicSharedMemorySize, SMEM_LIN);
    cudaFuncSetAttribute(k_gemm<DD>, cudaFuncAttributeMaxDynamicSharedMemorySize, SMEM_CNV);

    int mblocks = (N + 127) / 128;
    int x4 = N * FF / 4;

    // GEMM is launch #4 -> profiled by ncu
    k_prep<<<(N2 + 255) / 256, 256>>>(Wf, root, W, (__half*)pWfT, (__half*)pWc,
                                      (int*)pdg, N2);                             // 1
    k_xh<<<(x4 + 255) / 256, 256>>>(x, (__half*)pX, x4);                          // 2
    k_hist<<<(E / 2 + 255) / 256, 256>>>(ei, attr, (int*)pdg, E);                 // 3
    // h = relu(xh @ WfT + bf) -> fp16  (flags = relu | fp16out = 5)
    k_gemm<FF><<<dim3(mblocks, 1), 256, SMEM_LIN>>>((const __half*)pX, N,
                                                    (const __half*)pWfT, nullptr, nullptr,
                                                    nullptr, (__half*)pA, DD, bf, 5); // 4
    k_scanA<<<nb, 1024>>>((int*)pdg, (int*)pbp, N2);                              // 5
    k_scanC<<<nb, 1024>>>((int*)pdg, (int*)pbp, (int*)prp, (int*)pc, N2, nb);     // 6
    k_fill<<<(E / 2 + 255) / 256, 256>>>(ei, attr, (int*)pc, (int*)pcol, E);      // 7

    const __half* Wc0 = (const __half*)pWc;
    const __half* Wc1 = Wc0 + DD * DD;
    const __half* Wc2 = Wc0 + 2 * DD * DD;
    __half* hin = (__half*)pA;
    __half* hout = (__half*)pB;
    for (int it = 0; it < 3; it++) {
        // T = [h@root | h@W0 | h@W1]  (fp32 out)
        k_gemm<DD><<<dim3(mblocks, 3), 256, SMEM_CNV>>>(hin, N, Wc0, Wc1, Wc2,
                                                        (float*)pT, nullptr, 3 * DD,
                                                        nullptr, 0);
        int last = (it == 2);
        k_aggout<<<(N * 32 + 255) / 256, 256>>>((const float*)pT, (int*)prp, (int*)pcol,
                                                bias, last ? out : nullptr,
                                                last ? nullptr : hout, N, !last);
        __half* t = hin; hin = hout; hout = t;
    }
}

// round 16
// speedup vs baseline: 1.2681x; 1.2681x over previous
#include <cuda_runtime.h>
#include <cuda_fp16.h>
#include <cstdint>

#define NN 50000
#define EE 800000
#define DD 96
#define FF 128

// ---------------- scratch ----------------
// fused per-node buffer: [0:96) h | [96:192) a0 | [192:288) a1   (fp16)
__device__ __align__(16) __half g_H0[NN * 288];
__device__ __align__(16) __half g_H1[NN * 288];
__device__ __align__(16) __half g_xh[NN * FF];      // fp16 copy of x
__device__ __align__(16) __half g_WfT[FF * DD];     // fp16 transposed Wf
__device__ __align__(16) __half g_Wc[3 * DD * DD];  // fp16 [root ; W0 ; W1] rows = K
__device__ int g_deg[2 * NN];
__device__ int g_cur[2 * NN];
__device__ int g_rowptr[2 * NN + 1];
__device__ int g_col[EE];
__device__ int g_bpart[256];

// ---------------- prep ----------------
__global__ void k_prep(const float* __restrict__ Wf, const float* __restrict__ root,
                       const float* __restrict__ W,
                       __half* __restrict__ WfT, __half* __restrict__ Wc,
                       int* __restrict__ deg, int N2) {
    int i = blockIdx.x * blockDim.x + threadIdx.x;
    if (i < N2) deg[i] = 0;
    if (i < DD * FF) {
        int d = i >> 7, k = i & 127;
        WfT[k * DD + d] = __float2half_rn(Wf[i]);
    }
    if (i < 3 * DD * DD)
        Wc[i] = __float2half_rn((i < DD * DD) ? root[i] : W[i - DD * DD]);
}

// ---------------- x -> fp16 copy ----------------
__global__ void k_xh(const float* __restrict__ x, __half* __restrict__ xh, int total4) {
    int i = blockIdx.x * blockDim.x + threadIdx.x;
    if (i >= total4) return;
    float4 v = __ldg((const float4*)x + i);
    __half2* o = (__half2*)xh + 2 * i;
    o[0] = __floats2half2_rn(v.x, v.y);
    o[1] = __floats2half2_rn(v.z, v.w);
}

// ---------------- CSR build ----------------
__global__ void k_hist(const int* __restrict__ ei, const float* __restrict__ attr,
                       int* __restrict__ deg, int E) {
    int e = (blockIdx.x * blockDim.x + threadIdx.x) * 2;
    if (e >= E) return;
    int2 d2 = *(const int2*)(ei + E + e);
    float4 a4 = *(const float4*)(attr + 2 * e);
    atomicAdd(&deg[2 * d2.x + (a4.y > a4.x ? 1 : 0)], 1);
    if (e + 1 < E)
        atomicAdd(&deg[2 * d2.y + (a4.w > a4.z ? 1 : 0)], 1);
}

__global__ __launch_bounds__(1024) void k_scanA(const int* __restrict__ deg,
                                                int* __restrict__ bpart, int N2) {
    __shared__ int red[32];
    int t = threadIdx.x;
    int i = blockIdx.x * 1024 + t;
    int v = (i < N2) ? deg[i] : 0;
#pragma unroll
    for (int o = 16; o; o >>= 1) v += __shfl_down_sync(~0u, v, o);
    if ((t & 31) == 0) red[t >> 5] = v;
    __syncthreads();
    if (t < 32) {
        int s = red[t];
#pragma unroll
        for (int o = 16; o; o >>= 1) s += __shfl_down_sync(~0u, s, o);
        if (t == 0) bpart[blockIdx.x] = s;
    }
}

__global__ __launch_bounds__(1024) void k_scanC(const int* __restrict__ deg,
                                                const int* __restrict__ bpart,
                                                int* __restrict__ rowptr,
                                                int* __restrict__ cur, int N2, int nb) {
    __shared__ int sm[1024];
    __shared__ int bp[128];
    int t = threadIdx.x;
    if (t < 128) bp[t] = (t < nb) ? __ldg(&bpart[t]) : 0;
    __syncthreads();
#pragma unroll
    for (int o = 1; o < 128; o <<= 1) {
        int u = 0;
        if (t < 128 && t >= o) u = bp[t - o];
        __syncthreads();
        if (t < 128) bp[t] += u;
        __syncthreads();
    }
    int off = (blockIdx.x == 0) ? 0 : bp[blockIdx.x - 1];

    int i = blockIdx.x * 1024 + t;
    int v = (i < N2) ? deg[i] : 0;
    sm[t] = v;
    __syncthreads();
#pragma unroll
    for (int o = 1; o < 1024; o <<= 1) {
        int u = (t >= o) ? sm[t - o] : 0;
        __syncthreads();
        sm[t] += u;
        __syncthreads();
    }
    int pos = off + sm[t] - v;
    if (i < N2) {
        rowptr[i] = pos;
        cur[i] = pos;
        if (i == N2 - 1) rowptr[N2] = pos + v;
    }
}

__global__ void k_fill(const int* __restrict__ ei, const float* __restrict__ attr,
                       int* __restrict__ cur, int* __restrict__ col, int E) {
    int e = (blockIdx.x * blockDim.x + threadIdx.x) * 2;
    if (e >= E) return;
    int2 s2 = *(const int2*)(ei + e);
    int2 d2 = *(const int2*)(ei + E + e);
    float4 a4 = *(const float4*)(attr + 2 * e);
    {
        int seg = 2 * d2.x + (a4.y > a4.x ? 1 : 0);
        col[atomicAdd(&cur[seg], 1)] = s2.x;
    }
    if (e + 1 < E) {
        int seg = 2 * d2.y + (a4.w > a4.z ? 1 : 0);
        col[atomicAdd(&cur[seg], 1)] = s2.y;
    }
}

// ---------------- MMA primitives ----------------
__device__ __forceinline__ void mma_f16(float* c, const uint32_t* a, uint32_t b0, uint32_t b1) {
    asm volatile("mma.sync.aligned.m16n8k16.row.col.f32.f16.f16.f32 "
        "{%0,%1,%2,%3}, {%4,%5,%6,%7}, {%8,%9}, {%0,%1,%2,%3};"
        : "+f"(c[0]), "+f"(c[1]), "+f"(c[2]), "+f"(c[3])
        : "r"(a[0]), "r"(a[1]), "r"(a[2]), "r"(a[3]), "r"(b0), "r"(b1));
}
__device__ __forceinline__ void ldsm4(uint32_t* r, uint32_t addr) {
    asm volatile("ldmatrix.sync.aligned.m8n8.x4.shared.b16 {%0,%1,%2,%3}, [%4];"
        : "=r"(r[0]), "=r"(r[1]), "=r"(r[2]), "=r"(r[3]) : "r"(addr));
}
__device__ __forceinline__ void ldsm4t(uint32_t* r, uint32_t addr) {
    asm volatile("ldmatrix.sync.aligned.m8n8.x4.trans.shared.b16 {%0,%1,%2,%3}, [%4];"
        : "=r"(r[0]), "=r"(r[1]), "=r"(r[2]), "=r"(r[3]) : "r"(addr));
}
__device__ __forceinline__ void cp16(uint32_t saddr, const void* gaddr, int srcsize) {
    asm volatile("cp.async.cg.shared.global [%0], [%1], 16, %2;"
                 :: "r"(saddr), "l"(gaddr), "r"(srcsize));
}

#define BS_LDH 104

// ---------------- lin GEMM: full-K single-stage (K=128) ----------------
// flags: bit0 relu, bit2 fp16 out
template <int K>
__global__ __launch_bounds__(256, 3) void k_gemm(
    const __half* __restrict__ A, int M,
    const __half* __restrict__ B0,
    float* __restrict__ Cf, __half* __restrict__ Ch, int ldc,
    const float* __restrict__ bias, int flags)
{
    constexpr int AS_LDH = K + 8;
    constexpr int ASZH = 128 * AS_LDH;
    constexpr int APIECES = 128 * (K / 8);
    constexpr int BPIECES = K * 12;

    extern __shared__ char smem[];
    const __half* B = B0;

    int tid = threadIdx.x;
    int lane = tid & 31;
    int warp = tid >> 5;
    int g = lane >> 2, tig = lane & 3;
    int mw = warp & 3;
    int nw = warp >> 2;
    int rowblock = blockIdx.x * 128;

    uint32_t sbase = (uint32_t)__cvta_generic_to_shared(smem);

    for (int p = tid; p < APIECES; p += 256) {
        int row = p / (K / 8), kq = (p % (K / 8)) * 8;
        int gr = rowblock + row;
        cp16(sbase + (uint32_t)(row * AS_LDH + kq) * 2u,
             A + (size_t)gr * K + kq, (gr < M) ? 16 : 0);
    }
    for (int p = tid; p < BPIECES; p += 256) {
        int kr = p / 12, nq = (p % 12) * 8;
        cp16(sbase + (uint32_t)(ASZH + kr * BS_LDH + nq) * 2u,
             B + (size_t)kr * 96 + nq, 16);
    }
    asm volatile("cp.async.commit_group;" ::: "memory");

    float c[2][6][4];
#pragma unroll
    for (int i = 0; i < 2; i++)
#pragma unroll
        for (int j = 0; j < 6; j++)
#pragma unroll
            for (int q = 0; q < 4; q++) c[i][j][q] = 0.f;

    asm volatile("cp.async.wait_group 0;" ::: "memory");
    __syncthreads();

    uint32_t abase = sbase;
    uint32_t bbase = sbase + (uint32_t)ASZH * 2u;
#pragma unroll
    for (int k16 = 0; k16 < K; k16 += 16) {
        uint32_t a[2][4];
#pragma unroll
        for (int mt = 0; mt < 2; mt++) {
            int rb = mw * 32 + mt * 16;
            uint32_t addr = abase +
                (uint32_t)((rb + (lane & 15)) * AS_LDH + k16 + ((lane >> 4) << 3)) * 2u;
            ldsm4(a[mt], addr);
        }
        uint32_t b[3][4];
#pragma unroll
        for (int ntp = 0; ntp < 3; ntp++) {
            int cb = nw * 48 + ntp * 16;
            uint32_t addr = bbase +
                (uint32_t)((k16 + (lane & 15)) * BS_LDH + cb + ((lane & 16) ? 8 : 0)) * 2u;
            ldsm4t(b[ntp], addr);
        }
#pragma unroll
        for (int nt = 0; nt < 6; nt++) {
            uint32_t b0 = b[nt >> 1][(nt & 1) * 2];
            uint32_t b1 = b[nt >> 1][(nt & 1) * 2 + 1];
            mma_f16(c[0][nt], a[0], b0, b1);
            mma_f16(c[1][nt], a[1], b0, b1);
        }
    }

    int relu = flags & 1, h16 = flags & 4;
#pragma unroll
    for (int mt = 0; mt < 2; mt++) {
        int r0 = rowblock + mw * 32 + mt * 16 + g;
        int r1 = r0 + 8;
#pragma unroll
        for (int nt = 0; nt < 6; nt++) {
            int col = nw * 48 + nt * 8 + 2 * tig;
            float bx = 0.f, by = 0.f;
            if (bias) { bx = __ldg(bias + col); by = __ldg(bias + col + 1); }
            float v0 = c[mt][nt][0] + bx, v1 = c[mt][nt][1] + by;
            float v2 = c[mt][nt][2] + bx, v3 = c[mt][nt][3] + by;
            if (relu) {
                v0 = fmaxf(v0, 0.f); v1 = fmaxf(v1, 0.f);
                v2 = fmaxf(v2, 0.f); v3 = fmaxf(v3, 0.f);
            }
            if (h16) {
                if (r0 < M) *(__half2*)(Ch + (size_t)r0 * ldc + col) = __floats2half2_rn(v0, v1);
                if (r1 < M) *(__half2*)(Ch + (size_t)r1 * ldc + col) = __floats2half2_rn(v2, v3);
            } else {
                if (r0 < M) *(float2*)(Cf + (size_t)r0 * ldc + col) = make_float2(v0, v1);
                if (r1 < M) *(float2*)(Cf + (size_t)r1 * ldc + col) = make_float2(v2, v3);
            }
        }
    }
}

#define SMEM_LIN ((128 * (FF + 8) + FF * BS_LDH) * 2)

// ---------------- combine GEMM: K=288 as 3x96 double-buffered chunks ----------------
// A = H [M][288] fp16 (h|a0|a1); B = Wc [288][96] fp16; out = relu(bias + A@B)
#define CAS 104                   // A chunk row stride (halves)
#define CASZ (128 * CAS)          // 13312 halves
#define CBSZ (96 * BS_LDH)        // 9984 halves
#define SMEM_CNV ((2 * (CASZ + CBSZ)) * 2)

__global__ __launch_bounds__(256, 2) void k_cgemm(
    const __half* __restrict__ A, int M,
    const __half* __restrict__ B,
    float* __restrict__ Cf, __half* __restrict__ Ch, int ldc,
    const float* __restrict__ bias, int h16)
{
    extern __shared__ char smem[];
    int tid = threadIdx.x;
    int lane = tid & 31;
    int warp = tid >> 5;
    int g = lane >> 2, tig = lane & 3;
    int mw = warp & 3;
    int nw = warp >> 2;
    int rowblock = blockIdx.x * 128;

    uint32_t sbase = (uint32_t)__cvta_generic_to_shared(smem);
    // layout (halves): A0[CASZ] A1[CASZ] B0[CBSZ] B1[CBSZ]

    float c[2][6][4];
#pragma unroll
    for (int i = 0; i < 2; i++)
#pragma unroll
        for (int j = 0; j < 6; j++)
#pragma unroll
            for (int q = 0; q < 4; q++) c[i][j][q] = 0.f;

    // stage chunk 0
    for (int p = tid; p < 1536; p += 256) {
        int row = p / 12, kq = (p % 12) * 8;
        int gr = rowblock + row;
        cp16(sbase + (uint32_t)(row * CAS + kq) * 2u,
             A + (size_t)gr * 288 + kq, (gr < M) ? 16 : 0);
    }
    for (int p = tid; p < 1152; p += 256) {
        int kr = p / 12, nq = (p % 12) * 8;
        cp16(sbase + (uint32_t)(2 * CASZ + kr * BS_LDH + nq) * 2u,
             B + (size_t)kr * 96 + nq, 16);
    }
    asm volatile("cp.async.commit_group;" ::: "memory");

    int buf = 0;
#pragma unroll
    for (int ck = 0; ck < 3; ck++) {
        if (ck < 2) {
            int kb = (ck + 1) * 96;
            int nb_ = buf ^ 1;
            for (int p = tid; p < 1536; p += 256) {
                int row = p / 12, kq = (p % 12) * 8;
                int gr = rowblock + row;
                cp16(sbase + (uint32_t)(nb_ * CASZ + row * CAS + kq) * 2u,
                     A + (size_t)gr * 288 + kb + kq, (gr < M) ? 16 : 0);
            }
            for (int p = tid; p < 1152; p += 256) {
                int kr = p / 12, nq = (p % 12) * 8;
                cp16(sbase + (uint32_t)(2 * CASZ + nb_ * CBSZ + kr * BS_LDH + nq) * 2u,
                     B + (size_t)(kb + kr) * 96 + nq, 16);
            }
            asm volatile("cp.async.commit_group;" ::: "memory");
            asm volatile("cp.async.wait_group 1;" ::: "memory");
        } else {
            asm volatile("cp.async.wait_group 0;" ::: "memory");
        }
        __syncthreads();

        uint32_t abase = sbase + (uint32_t)(buf * CASZ) * 2u;
        uint32_t bbase = sbase + (uint32_t)(2 * CASZ + buf * CBSZ) * 2u;
#pragma unroll
        for (int k16 = 0; k16 < 96; k16 += 16) {
            uint32_t a[2][4];
#pragma unroll
            for (int mt = 0; mt < 2; mt++) {
                int rb = mw * 32 + mt * 16;
                uint32_t addr = abase +
                    (uint32_t)((rb + (lane & 15)) * CAS + k16 + ((lane >> 4) << 3)) * 2u;
                ldsm4(a[mt], addr);
            }
            uint32_t b[3][4];
#pragma unroll
            for (int ntp = 0; ntp < 3; ntp++) {
                int cb = nw * 48 + ntp * 16;
                uint32_t addr = bbase +
                    (uint32_t)((k16 + (lane & 15)) * BS_LDH + cb + ((lane & 16) ? 8 : 0)) * 2u;
                ldsm4t(b[ntp], addr);
            }
#pragma unroll
            for (int nt = 0; nt < 6; nt++) {
                uint32_t b0 = b[nt >> 1][(nt & 1) * 2];
                uint32_t b1 = b[nt >> 1][(nt & 1) * 2 + 1];
                mma_f16(c[0][nt], a[0], b0, b1);
                mma_f16(c[1][nt], a[1], b0, b1);
            }
        }
        __syncthreads();
        buf ^= 1;
    }

#pragma unroll
    for (int mt = 0; mt < 2; mt++) {
        int r0 = rowblock + mw * 32 + mt * 16 + g;
        int r1 = r0 + 8;
#pragma unroll
        for (int nt = 0; nt < 6; nt++) {
            int col = nw * 48 + nt * 8 + 2 * tig;
            float bx = __ldg(bias + col), by = __ldg(bias + col + 1);
            float v0 = fmaxf(c[mt][nt][0] + bx, 0.f);
            float v1 = fmaxf(c[mt][nt][1] + by, 0.f);
            float v2 = fmaxf(c[mt][nt][2] + bx, 0.f);
            float v3 = fmaxf(c[mt][nt][3] + by, 0.f);
            if (h16) {
                if (r0 < M) *(__half2*)(Ch + (size_t)r0 * ldc + col) = __floats2half2_rn(v0, v1);
                if (r1 < M) *(__half2*)(Ch + (size_t)r1 * ldc + col) = __floats2half2_rn(v2, v3);
            } else {
                if (r0 < M) *(float2*)(Cf + (size_t)r0 * ldc + col) = make_float2(v0, v1);
                if (r1 < M) *(float2*)(Cf + (size_t)r1 * ldc + col) = make_float2(v2, v3);
            }
        }
    }
}

// ---------------- agg: gather fp16 h, write fp16 means a0/a1 into H ----------------
// warp per node; lanes 0..23 own 8B (4 halves) of the 192B h-row
__global__ void k_agg(__half* __restrict__ H, const int* __restrict__ rowptr,
                      const int* __restrict__ col, int N) {
    int warpi = (blockIdx.x * blockDim.x + threadIdx.x) >> 5;
    int lane = threadIdx.x & 31;
    if (warpi >= N) return;
    int n = warpi;
    int e00 = __ldg(&rowptr[2 * n]);
    int e01 = __ldg(&rowptr[2 * n + 1]);
    int e11 = __ldg(&rowptr[2 * n + 2]);
    int cl = (lane < 24) ? lane : 23;

    float x0 = 0.f, x1 = 0.f, x2 = 0.f, x3 = 0.f;
    float y0 = 0.f, y1 = 0.f, y2 = 0.f, y3 = 0.f;

    int e = e00;
    for (; e + 3 < e01; e += 4) {
        const uint2* p0 = (const uint2*)(H + (size_t)__ldg(&col[e])     * 288) + cl;
        const uint2* p1 = (const uint2*)(H + (size_t)__ldg(&col[e + 1]) * 288) + cl;
        const uint2* p2 = (const uint2*)(H + (size_t)__ldg(&col[e + 2]) * 288) + cl;
        const uint2* p3 = (const uint2*)(H + (size_t)__ldg(&col[e + 3]) * 288) + cl;
        uint2 v0 = __ldg(p0), v1 = __ldg(p1), v2 = __ldg(p2), v3 = __ldg(p3);
        float2 f;
        f = __half22float2(*(__half2*)&v0.x); x0 += f.x; x1 += f.y;
        f = __half22float2(*(__half2*)&v0.y); x2 += f.x; x3 += f.y;
        f = __half22float2(*(__half2*)&v1.x); x0 += f.x; x1 += f.y;
        f = __half22float2(*(__half2*)&v1.y); x2 += f.x; x3 += f.y;
        f = __half22float2(*(__half2*)&v2.x); x0 += f.x; x1 += f.y;
        f = __half22float2(*(__half2*)&v2.y); x2 += f.x; x3 += f.y;
        f = __half22float2(*(__half2*)&v3.x); x0 += f.x; x1 += f.y;
        f = __half22float2(*(__half2*)&v3.y); x2 += f.x; x3 += f.y;
    }
    for (; e < e01; e++) {
        uint2 v = __ldg((const uint2*)(H + (size_t)__ldg(&col[e]) * 288) + cl);
        float2 f;
        f = __half22float2(*(__half2*)&v.x); x0 += f.x; x1 += f.y;
        f = __half22float2(*(__half2*)&v.y); x2 += f.x; x3 += f.y;
    }
    e = e01;
    for (; e + 3 < e11; e += 4) {
        const uint2* p0 = (const uint2*)(H + (size_t)__ldg(&col[e])     * 288) + cl;
        const uint2* p1 = (const uint2*)(H + (size_t)__ldg(&col[e + 1]) * 288) + cl;
        const uint2* p2 = (const uint2*)(H + (size_t)__ldg(&col[e + 2]) * 288) + cl;
        const uint2* p3 = (const uint2*)(H + (size_t)__ldg(&col[e + 3]) * 288) + cl;
        uint2 v0 = __ldg(p0), v1 = __ldg(p1), v2 = __ldg(p2), v3 = __ldg(p3);
        float2 f;
        f = __half22float2(*(__half2*)&v0.x); y0 += f.x; y1 += f.y;
        f = __half22float2(*(__half2*)&v0.y); y2 += f.x; y3 += f.y;
        f = __half22float2(*(__half2*)&v1.x); y0 += f.x; y1 += f.y;
        f = __half22float2(*(__half2*)&v1.y); y2 += f.x; y3 += f.y;
        f = __half22float2(*(__half2*)&v2.x); y0 += f.x; y1 += f.y;
        f = __half22float2(*(__half2*)&v2.y); y2 += f.x; y3 += f.y;
        f = __half22float2(*(__half2*)&v3.x); y0 += f.x; y1 += f.y;
        f = __half22float2(*(__half2*)&v3.y); y2 += f.x; y3 += f.y;
    }
    for (; e < e11; e++) {
        uint2 v = __ldg((const uint2*)(H + (size_t)__ldg(&col[e]) * 288) + cl);
        float2 f;
        f = __half22float2(*(__half2*)&v.x); y0 += f.x; y1 += f.y;
        f = __half22float2(*(__half2*)&v.y); y2 += f.x; y3 += f.y;
    }

    if (lane < 24) {
        float i0 = 1.f / fmaxf((float)(e01 - e00), 1.f);
        float i1 = 1.f / fmaxf((float)(e11 - e01), 1.f);
        uint2 w;
        __half2 ha = __floats2half2_rn(x0 * i0, x1 * i0);
        __half2 hb = __floats2half2_rn(x2 * i0, x3 * i0);
        w.x = *(uint32_t*)&ha; w.y = *(uint32_t*)&hb;
        *((uint2*)(H + (size_t)n * 288 + 96) + lane) = w;
        ha = __floats2half2_rn(y0 * i1, y1 * i1);
        hb = __floats2half2_rn(y2 * i1, y3 * i1);
        w.x = *(uint32_t*)&ha; w.y = *(uint32_t*)&hb;
        *((uint2*)(H + (size_t)n * 288 + 192) + lane) = w;
    }
}

// ---------------- launch ----------------
extern "C" void kernel_launch(void* const* d_in, const int* in_sizes, int n_in,
                              void* d_out, int out_size) {
    const float* x    = (const float*)d_in[0];
    const int*   ei   = (const int*)d_in[1];
    const float* attr = (const float*)d_in[2];
    const float* Wf   = (const float*)d_in[3];
    const float* bf   = (const float*)d_in[4];
    const float* W    = (const float*)d_in[5];
    const float* root = (const float*)d_in[6];
    const float* bias = (const float*)d_in[7];
    float* out = (float*)d_out;

    int E = in_sizes[1] / 2;
    int N = in_sizes[0] / FF;
    int N2 = 2 * N;
    int nb = (N2 + 1023) / 1024;

    void *pH0, *pH1, *pX, *pWfT, *pWc, *pdg, *prp, *pc, *pcol, *pbp;
    cudaGetSymbolAddress(&pH0, g_H0);
    cudaGetSymbolAddress(&pH1, g_H1);
    cudaGetSymbolAddress(&pX, g_xh);
    cudaGetSymbolAddress(&pWfT, g_WfT);
    cudaGetSymbolAddress(&pWc, g_Wc);
    cudaGetSymbolAddress(&pdg, g_deg);
    cudaGetSymbolAddress(&prp, g_rowptr);
    cudaGetSymbolAddress(&pc, g_cur);
    cudaGetSymbolAddress(&pcol, g_col);
    cudaGetSymbolAddress(&pbp, g_bpart);

    cudaFuncSetAttribute(k_gemm<FF>, cudaFuncAttributeMaxDynamicSharedMemorySize, SMEM_LIN);
    cudaFuncSetAttribute(k_cgemm, cudaFuncAttributeMaxDynamicSharedMemorySize, SMEM_CNV);

    int mblocks = (N + 127) / 128;
    int x4 = N * FF / 4;

    // GEMM is launch #4 -> profiled by ncu
    k_prep<<<(N2 + 255) / 256, 256>>>(Wf, root, W, (__half*)pWfT, (__half*)pWc,
                                      (int*)pdg, N2);                             // 1
    k_xh<<<(x4 + 255) / 256, 256>>>(x, (__half*)pX, x4);                          // 2
    k_hist<<<(E / 2 + 255) / 256, 256>>>(ei, attr, (int*)pdg, E);                 // 3
    // h = relu(xh @ WfT + bf) -> fp16 into H0 slot 0 (ldc = 288)
    k_gemm<FF><<<dim3(mblocks, 1), 256, SMEM_LIN>>>((const __half*)pX, N,
                                                    (const __half*)pWfT,
                                                    nullptr, (__half*)pH0, 288, bf, 5); // 4
    k_scanA<<<nb, 1024>>>((int*)pdg, (int*)pbp, N2);                              // 5
    k_scanC<<<nb, 1024>>>((int*)pdg, (int*)pbp, (int*)prp, (int*)pc, N2, nb);     // 6
    k_fill<<<(E / 2 + 255) / 256, 256>>>(ei, attr, (int*)pc, (int*)pcol, E);      // 7

    __half* Hin = (__half*)pH0;
    __half* Hout = (__half*)pH1;
    for (int it = 0; it < 3; it++) {
        k_agg<<<(N * 32 + 255) / 256, 256>>>(Hin, (int*)prp, (int*)pcol, N);
        int last = (it == 2);
        // out_h = relu(bias + [h|a0|a1] @ [root;W0;W1])
        k_cgemm<<<mblocks, 256, SMEM_CNV>>>(Hin, N, (const __half*)pWc,
                                            last ? out : nullptr,
                                            last ? nullptr : Hout,
                                            last ? DD : 288,
                                            bias, last ? 0 : 1);
        __half* t = Hin; Hin = Hout; Hout = t;
    }
}